// round 11
// baseline (speedup 1.0000x reference)
#include <cuda_runtime.h>
#include <cuda.h>
#include <cuda_fp16.h>
#include <cstdint>

// ============================================================================
// out[m,n] = sum_k A[m,k] * (q[n,k]-zeros[n,k/128])*scales[n,k/128] + bias[n]
// M=2048, K=4096, N=4096, G=32.
// Pass 1 (fused, 16 elem/thread): A fp32->fp16, W dequant->fp16, + reset queue.
// Pass 2: PERSISTENT fp16 GEMM, 592 CTAs (4/SM), atomic tile queue, and
//         R11: pipelined tile transition — next tile's prologue TMA issues
//         BEFORE the current tile's epilogue, hiding prologue latency + keeping
//         the tensor pipe fed across tile boundaries.
// Evidence: tensor-busy invariant ~114us (R8/R9/R10); idle = 13.5% slot
// quantization (hard ceiling 86.5%) + ~6% tile-transition bubbles (this fix).
// ============================================================================

static constexpr int Mdim = 2048, Kdim = 4096, Ndim = 4096, Gdim = 32;

static constexpr int TILE_M = 64, TILE_N = 128, TILE_K = 64;
static constexpr int STAGES = 2;
static constexpr int A_STAGE_BYTES = TILE_M * TILE_K * 2;  // 8192
static constexpr int B_STAGE_BYTES = TILE_N * TILE_K * 2;  // 16384
static constexpr int STAGE_BYTES = A_STAGE_BYTES + B_STAGE_BYTES;  // 24576
static constexpr int OFF_FULL  = 0;    // 2 x 8B
static constexpr int OFF_TILE  = 16;   // 4B broadcast slot
static constexpr int OFF_STAGE = 1024; // 1024-aligned for SW128
static constexpr int SMEM_TOTAL = OFF_STAGE + STAGES * STAGE_BYTES;  // 50176
static constexpr int NUM_SLABS = Kdim / TILE_K;  // 64
static constexpr int TILES_N = Ndim / TILE_N;    // 32
static constexpr int NUM_TILES = (Mdim / TILE_M) * TILES_N;  // 1024
static constexpr int GRID_GEMM = 592;            // 4 per SM x 148 SMs

static __device__ __align__(1024) __half g_A16[(size_t)Mdim * Kdim];
static __device__ __align__(1024) __half g_W16[(size_t)Ndim * Kdim];
static __device__ unsigned g_tile_counter;

#define DEVINL __device__ __forceinline__

DEVINL uint32_t smem_u32(const void* p) {
    uint32_t a;
    asm("{ .reg .u64 t; cvta.to.shared.u64 t, %1; cvt.u32.u64 %0, t; }"
        : "=r"(a) : "l"(p));
    return a;
}
DEVINL void mbar_init(uint32_t a, uint32_t cnt) {
    asm volatile("mbarrier.init.shared.b64 [%0], %1;" :: "r"(a), "r"(cnt) : "memory");
}
DEVINL void mbar_expect_tx(uint32_t a, uint32_t bytes) {
    asm volatile("mbarrier.arrive.expect_tx.shared.b64 _, [%0], %1;"
                 :: "r"(a), "r"(bytes) : "memory");
}
DEVINL void mbar_wait(uint32_t a, uint32_t parity) {
    asm volatile(
        "{\n\t.reg .pred P;\n\t"
        "LAB_%=:\n\t"
        "mbarrier.try_wait.parity.acquire.cta.shared::cta.b64 P, [%0], %1, 0x989680;\n\t"
        "@!P bra LAB_%=;\n\t"
        "}" :: "r"(a), "r"(parity) : "memory");
}
DEVINL void tma_2d(uint32_t smem, const void* map, int x, int y, uint32_t bar) {
    asm volatile(
        "cp.async.bulk.tensor.2d.shared::cta.global.tile.mbarrier::complete_tx::bytes "
        "[%0], [%1, {%2, %3}], [%4];"
        :: "r"(smem), "l"(map), "r"(x), "r"(y), "r"(bar) : "memory");
}
DEVINL void fence_proxy_async() {
    asm volatile("fence.proxy.async.shared::cta;" ::: "memory");
}
DEVINL void ldsm_x4(uint32_t& r0, uint32_t& r1, uint32_t& r2, uint32_t& r3,
                    uint32_t addr) {
    asm volatile("ldmatrix.sync.aligned.m8n8.x4.shared.b16 {%0,%1,%2,%3}, [%4];"
                 : "=r"(r0), "=r"(r1), "=r"(r2), "=r"(r3) : "r"(addr));
}
DEVINL void mma16816(float* c, const uint32_t* a, uint32_t b0, uint32_t b1) {
    asm volatile(
        "mma.sync.aligned.m16n8k16.row.col.f32.f16.f16.f32 "
        "{%0,%1,%2,%3}, {%4,%5,%6,%7}, {%8,%9}, {%0,%1,%2,%3};"
        : "+f"(c[0]), "+f"(c[1]), "+f"(c[2]), "+f"(c[3])
        : "r"(a[0]), "r"(a[1]), "r"(a[2]), "r"(a[3]), "r"(b0), "r"(b1));
}

// ---------------------------- Pass 1: fused, 16 elems/thread ----------------
static constexpr int NBLK_A = (Mdim * Kdim / 16) / 256;  // 2048
static constexpr int NBLK_W = (Ndim * Kdim / 16) / 256;  // 4096

__global__ void __launch_bounds__(256) pass1_kernel(
    const float* __restrict__ A, const int* __restrict__ q,
    const float* __restrict__ sc, const float* __restrict__ zr,
    __half* __restrict__ A16, __half* __restrict__ W16) {
    int bid = blockIdx.x;
    if (bid == 0 && threadIdx.x == 0) g_tile_counter = 0;  // reset work queue
    if (bid < NBLK_A) {
        int t = bid * 256 + threadIdx.x;
        const float4* a4 = reinterpret_cast<const float4*>(A) + (size_t)t * 4;
        float4 v[4];
        #pragma unroll
        for (int i = 0; i < 4; i++) v[i] = a4[i];  // 4 LDG.128 in flight
        #pragma unroll
        for (int i = 0; i < 4; i += 2) {
            __half2 h[4];
            h[0] = __floats2half2_rn(v[i].x, v[i].y);
            h[1] = __floats2half2_rn(v[i].z, v[i].w);
            h[2] = __floats2half2_rn(v[i + 1].x, v[i + 1].y);
            h[3] = __floats2half2_rn(v[i + 1].z, v[i + 1].w);
            reinterpret_cast<uint4*>(A16)[(size_t)t * 2 + (i >> 1)] =
                *reinterpret_cast<uint4*>(h);
        }
    } else {
        int t = (bid - NBLK_A) * 256 + threadIdx.x;
        int k16 = t & (Kdim / 16 - 1);
        int n = t >> 8;
        int g = k16 >> 3;
        float s = sc[n * Gdim + g];
        float z = zr[n * Gdim + g];
        const int4* qp = reinterpret_cast<const int4*>(q) + (size_t)t * 4;
        int4 v[4];
        #pragma unroll
        for (int i = 0; i < 4; i++) v[i] = qp[i];
        #pragma unroll
        for (int i = 0; i < 4; i += 2) {
            __half2 h[4];
            h[0] = __floats2half2_rn(((float)v[i].x - z) * s, ((float)v[i].y - z) * s);
            h[1] = __floats2half2_rn(((float)v[i].z - z) * s, ((float)v[i].w - z) * s);
            h[2] = __floats2half2_rn(((float)v[i+1].x - z) * s, ((float)v[i+1].y - z) * s);
            h[3] = __floats2half2_rn(((float)v[i+1].z - z) * s, ((float)v[i+1].w - z) * s);
            reinterpret_cast<uint4*>(W16)[(size_t)t * 2 + (i >> 1)] =
                *reinterpret_cast<uint4*>(h);
        }
    }
}

// ---------------------------- Pass 2: persistent GEMM -----------------------
// 592 persistent CTAs, atomic tile queue. Tile transitions pipelined: next
// tile's prologue TMA issues before current tile's epilogue stores.
__global__ void __launch_bounds__(256, 4)
gemm_f16_kernel(const __grid_constant__ CUtensorMap tmA,
                const __grid_constant__ CUtensorMap tmB,
                const float* __restrict__ bias,
                float* __restrict__ out) {
    extern __shared__ char smem[];
    uint32_t sb = smem_u32(smem);
    int tid = threadIdx.x, wid = tid >> 5, lane = tid & 31;
    int wm = wid >> 2, wn = wid & 3;  // warp coords: 2(M) x 4(N)

    if (tid == 0) {
        #pragma unroll
        for (int i = 0; i < STAGES; i++) mbar_init(sb + OFF_FULL + i * 8, 1);
        fence_proxy_async();
    }

    // ldmatrix address components (SW128: xor = (lane&7)*16)
    int a_row = wm * 32 + (lane & 15);                      // + mb*16
    int a_khalf = (lane & 16);
    int b_row = wn * 32 + ((lane & 16) >> 1) + (lane & 7);  // + j*16
    int b_khalf = (lane & 8) << 1;
    int sw_xor = (lane & 7) * 16;

    uint32_t aRowOff[2], bRowOff[2];
    #pragma unroll
    for (int mb = 0; mb < 2; mb++) aRowOff[mb] = (uint32_t)(a_row + mb * 16) * 128;
    #pragma unroll
    for (int j = 0; j < 2; j++)
        bRowOff[j] = A_STAGE_BYTES + (uint32_t)(b_row + j * 16) * 128;

    unsigned* tileSlot = reinterpret_cast<unsigned*>(smem + OFF_TILE);
    int gr = lane >> 2, gc = (lane & 3) * 2;

    // ---- initial tile grab + prologue ----
    __syncthreads();  // mbar_init visible to all
    if (tid == 0) *tileSlot = atomicAdd(&g_tile_counter, 1u);
    __syncthreads();
    unsigned t = *tileSlot;
    if (tid == 0 && t < NUM_TILES) {
        int bm = t >> 5, bn = t & (TILES_N - 1);
        #pragma unroll
        for (int j = 0; j < STAGES; j++) {
            uint32_t fullb = sb + OFF_FULL + j * 8;
            uint32_t sA = sb + OFF_STAGE + j * STAGE_BYTES;
            mbar_expect_tx(fullb, STAGE_BYTES);
            tma_2d(sA, &tmA, j * TILE_K, bm * TILE_M, fullb);
            tma_2d(sA + A_STAGE_BYTES, &tmB, j * TILE_K, bn * TILE_N, fullb);
        }
    }

    while (t < NUM_TILES) {
        int bm = t >> 5, bn = t & (TILES_N - 1);

        float acc[2][4][4];
        #pragma unroll
        for (int mb = 0; mb < 2; mb++)
            #pragma unroll
            for (int nb = 0; nb < 4; nb++)
                #pragma unroll
                for (int i = 0; i < 4; i++) acc[mb][nb][i] = 0.0f;

        for (int s = 0; s < NUM_SLABS; s++) {
            int st = s & 1;
            int ph = (s >> 1) & 1;
            mbar_wait(sb + OFF_FULL + st * 8, ph);
            uint32_t base = sb + OFF_STAGE + st * STAGE_BYTES;

            #pragma unroll
            for (int ks = 0; ks < 4; ks++) {
                int koffA = ((ks * 32) | a_khalf) ^ sw_xor;
                int koffB = ((ks * 32) | b_khalf) ^ sw_xor;
                uint32_t a[2][4], b[2][4];
                #pragma unroll
                for (int mb = 0; mb < 2; mb++)
                    ldsm_x4(a[mb][0], a[mb][1], a[mb][2], a[mb][3],
                            base + aRowOff[mb] + koffA);
                #pragma unroll
                for (int j = 0; j < 2; j++)
                    ldsm_x4(b[j][0], b[j][1], b[j][2], b[j][3],
                            base + bRowOff[j] + koffB);
                #pragma unroll
                for (int mb = 0; mb < 2; mb++) {
                    #pragma unroll
                    for (int nb = 0; nb < 4; nb++) {
                        int j = nb >> 1, h = (nb & 1) * 2;
                        mma16816(acc[mb][nb], a[mb], b[j][h], b[j][h + 1]);
                    }
                }
            }

            // stage consumed -> barrier; tid0 refills for slab s+2 (this tile)
            __syncthreads();
            if (tid == 0 && s + STAGES < NUM_SLABS) {
                uint32_t fullb = sb + OFF_FULL + st * 8;
                mbar_expect_tx(fullb, STAGE_BYTES);
                tma_2d(base, &tmA, (s + STAGES) * TILE_K, bm * TILE_M, fullb);
                tma_2d(base + A_STAGE_BYTES, &tmB, (s + STAGES) * TILE_K,
                       bn * TILE_N, fullb);
            }
        }
        // All slabs consumed; slab-63's __syncthreads fenced every LDSM read,
        // so both stages are free. Grab next tile and issue ITS prologue
        // before the epilogue -> TMA flies while we store results.
        if (tid == 0) *tileSlot = atomicAdd(&g_tile_counter, 1u);
        __syncthreads();
        unsigned t2 = *tileSlot;
        if (tid == 0 && t2 < NUM_TILES) {
            int bm2 = t2 >> 5, bn2 = t2 & (TILES_N - 1);
            #pragma unroll
            for (int j = 0; j < STAGES; j++) {
                uint32_t fullb = sb + OFF_FULL + j * 8;
                uint32_t sA = sb + OFF_STAGE + j * STAGE_BYTES;
                mbar_expect_tx(fullb, STAGE_BYTES);
                tma_2d(sA, &tmA, j * TILE_K, bm2 * TILE_M, fullb);
                tma_2d(sA + A_STAGE_BYTES, &tmB, j * TILE_K, bn2 * TILE_N, fullb);
            }
        }

        // ---------------- epilogue (no smem; overlaps next prologue) --------
        #pragma unroll
        for (int mb = 0; mb < 2; mb++) {
            int row = bm * TILE_M + wm * 32 + mb * 16 + gr;
            float* orow0 = out + (size_t)row * Ndim;
            float* orow1 = out + (size_t)(row + 8) * Ndim;
            #pragma unroll
            for (int nb = 0; nb < 4; nb++) {
                int col = bn * TILE_N + wn * 32 + nb * 8 + gc;
                float2 bv = __ldg(reinterpret_cast<const float2*>(bias + col));
                float2 v0 = {acc[mb][nb][0] + bv.x, acc[mb][nb][1] + bv.y};
                float2 v1 = {acc[mb][nb][2] + bv.x, acc[mb][nb][3] + bv.y};
                *reinterpret_cast<float2*>(orow0 + col) = v0;
                *reinterpret_cast<float2*>(orow1 + col) = v1;
            }
        }

        t = t2;
    }
}

// ---------------------------- host launch -----------------------------------
typedef CUresult (*PFN_encodeTiled)(
    CUtensorMap*, CUtensorMapDataType, cuuint32_t, void*,
    const cuuint64_t*, const cuuint64_t*, const cuuint32_t*, const cuuint32_t*,
    CUtensorMapInterleave, CUtensorMapSwizzle, CUtensorMapL2promotion,
    CUtensorMapFloatOOBfill);

extern "C" void kernel_launch(void* const* d_in, const int* in_sizes, int n_in,
                              void* d_out, int out_size) {
    const float* A      = (const float*)d_in[0];
    const int*   qw     = (const int*)  d_in[1];
    const float* scales = (const float*)d_in[2];
    const float* zeros  = (const float*)d_in[3];
    const float* bias   = (const float*)d_in[4];
    float*       out    = (float*)d_out;

    void *pA16 = nullptr, *pW16 = nullptr;
    cudaGetSymbolAddress(&pA16, g_A16);
    cudaGetSymbolAddress(&pW16, g_W16);
    __half* A16 = (__half*)pA16;
    __half* W16 = (__half*)pW16;

    pass1_kernel<<<NBLK_A + NBLK_W, 256>>>(A, qw, scales, zeros, A16, W16);

    PFN_encodeTiled enc = nullptr;
    cudaDriverEntryPointQueryResult qres;
    cudaGetDriverEntryPointByVersion("cuTensorMapEncodeTiled", (void**)&enc,
                                     12000, cudaEnableDefault, &qres);
    if (!enc) return;

    CUtensorMap tmA, tmB;
    {
        cuuint64_t dims[2]    = {(cuuint64_t)Kdim, (cuuint64_t)Mdim};
        cuuint64_t strides[1] = {(cuuint64_t)Kdim * 2};
        cuuint32_t box[2]     = {TILE_K, TILE_M};  // {64, 64}
        cuuint32_t es[2]      = {1, 1};
        enc(&tmA, CU_TENSOR_MAP_DATA_TYPE_FLOAT16, 2, A16, dims, strides, box, es,
            CU_TENSOR_MAP_INTERLEAVE_NONE, CU_TENSOR_MAP_SWIZZLE_128B,
            CU_TENSOR_MAP_L2_PROMOTION_L2_128B, CU_TENSOR_MAP_FLOAT_OOB_FILL_NONE);
    }
    {
        cuuint64_t dims[2]    = {(cuuint64_t)Kdim, (cuuint64_t)Ndim};
        cuuint64_t strides[1] = {(cuuint64_t)Kdim * 2};
        cuuint32_t box[2]     = {TILE_K, TILE_N};  // {64, 128}
        cuuint32_t es[2]      = {1, 1};
        enc(&tmB, CU_TENSOR_MAP_DATA_TYPE_FLOAT16, 2, W16, dims, strides, box, es,
            CU_TENSOR_MAP_INTERLEAVE_NONE, CU_TENSOR_MAP_SWIZZLE_128B,
            CU_TENSOR_MAP_L2_PROMOTION_L2_128B, CU_TENSOR_MAP_FLOAT_OOB_FILL_NONE);
    }

    cudaFuncSetAttribute(gemm_f16_kernel,
                         cudaFuncAttributeMaxDynamicSharedMemorySize, SMEM_TOTAL);
    gemm_f16_kernel<<<GRID_GEMM, 256, SMEM_TOTAL>>>(tmA, tmB, bias, out);
}

// round 12
// speedup vs baseline: 1.0365x; 1.0365x over previous
#include <cuda_runtime.h>
#include <cuda.h>
#include <cuda_fp16.h>
#include <cstdint>

// ============================================================================
// out[m,n] = sum_k A[m,k] * (q[n,k]-zeros[n,k/128])*scales[n,k/128] + bias[n]
// M=2048, K=4096, N=4096, G=32.
// Pass 1 (fused, 16 elem/thread): A fp32->fp16, W dequant->fp16.
// Pass 2: fp16 GEMM, mma.sync.m16n8k16. R12: TILE 128x64, 128 threads /
//         4 warps (2x2), warp tile 64x32, 4 CTAs/SM, static grid.
// Evidence: R9/R11 L1=83-84% == smem crossbar co-bound (4.3GB LDSM @34TB/s =
// 126us > 114us tensor-busy). New warp tiling: 48KB/24KB tile (2.0x ampl) ->
// 3.1GB = 92us, smem unbinds; 4 independent warps per SMSP.
// ============================================================================

static constexpr int Mdim = 2048, Kdim = 4096, Ndim = 4096, Gdim = 32;

static constexpr int TILE_M = 128, TILE_N = 64, TILE_K = 64;
static constexpr int STAGES = 2;
static constexpr int A_STAGE_BYTES = TILE_M * TILE_K * 2;  // 16384
static constexpr int B_STAGE_BYTES = TILE_N * TILE_K * 2;  // 8192
static constexpr int STAGE_BYTES = A_STAGE_BYTES + B_STAGE_BYTES;  // 24576
static constexpr int OFF_FULL  = 0;    // 2 x 8B
static constexpr int OFF_STAGE = 1024; // 1024-aligned for SW128
static constexpr int SMEM_TOTAL = OFF_STAGE + STAGES * STAGE_BYTES;  // 50176
static constexpr int NUM_SLABS = Kdim / TILE_K;  // 64

static __device__ __align__(1024) __half g_A16[(size_t)Mdim * Kdim];
static __device__ __align__(1024) __half g_W16[(size_t)Ndim * Kdim];

#define DEVINL __device__ __forceinline__

DEVINL uint32_t smem_u32(const void* p) {
    uint32_t a;
    asm("{ .reg .u64 t; cvta.to.shared.u64 t, %1; cvt.u32.u64 %0, t; }"
        : "=r"(a) : "l"(p));
    return a;
}
DEVINL void mbar_init(uint32_t a, uint32_t cnt) {
    asm volatile("mbarrier.init.shared.b64 [%0], %1;" :: "r"(a), "r"(cnt) : "memory");
}
DEVINL void mbar_expect_tx(uint32_t a, uint32_t bytes) {
    asm volatile("mbarrier.arrive.expect_tx.shared.b64 _, [%0], %1;"
                 :: "r"(a), "r"(bytes) : "memory");
}
DEVINL void mbar_wait(uint32_t a, uint32_t parity) {
    asm volatile(
        "{\n\t.reg .pred P;\n\t"
        "LAB_%=:\n\t"
        "mbarrier.try_wait.parity.acquire.cta.shared::cta.b64 P, [%0], %1, 0x989680;\n\t"
        "@!P bra LAB_%=;\n\t"
        "}" :: "r"(a), "r"(parity) : "memory");
}
DEVINL void tma_2d(uint32_t smem, const void* map, int x, int y, uint32_t bar) {
    asm volatile(
        "cp.async.bulk.tensor.2d.shared::cta.global.tile.mbarrier::complete_tx::bytes "
        "[%0], [%1, {%2, %3}], [%4];"
        :: "r"(smem), "l"(map), "r"(x), "r"(y), "r"(bar) : "memory");
}
DEVINL void fence_proxy_async() {
    asm volatile("fence.proxy.async.shared::cta;" ::: "memory");
}
DEVINL void ldsm_x4(uint32_t& r0, uint32_t& r1, uint32_t& r2, uint32_t& r3,
                    uint32_t addr) {
    asm volatile("ldmatrix.sync.aligned.m8n8.x4.shared.b16 {%0,%1,%2,%3}, [%4];"
                 : "=r"(r0), "=r"(r1), "=r"(r2), "=r"(r3) : "r"(addr));
}
DEVINL void mma16816(float* c, const uint32_t* a, uint32_t b0, uint32_t b1) {
    asm volatile(
        "mma.sync.aligned.m16n8k16.row.col.f32.f16.f16.f32 "
        "{%0,%1,%2,%3}, {%4,%5,%6,%7}, {%8,%9}, {%0,%1,%2,%3};"
        : "+f"(c[0]), "+f"(c[1]), "+f"(c[2]), "+f"(c[3])
        : "r"(a[0]), "r"(a[1]), "r"(a[2]), "r"(a[3]), "r"(b0), "r"(b1));
}

// ---------------------------- Pass 1: fused, 16 elems/thread ----------------
static constexpr int NBLK_A = (Mdim * Kdim / 16) / 256;  // 2048
static constexpr int NBLK_W = (Ndim * Kdim / 16) / 256;  // 4096

__global__ void __launch_bounds__(256) pass1_kernel(
    const float* __restrict__ A, const int* __restrict__ q,
    const float* __restrict__ sc, const float* __restrict__ zr,
    __half* __restrict__ A16, __half* __restrict__ W16) {
    int bid = blockIdx.x;
    if (bid < NBLK_A) {
        int t = bid * 256 + threadIdx.x;
        const float4* a4 = reinterpret_cast<const float4*>(A) + (size_t)t * 4;
        float4 v[4];
        #pragma unroll
        for (int i = 0; i < 4; i++) v[i] = a4[i];  // 4 LDG.128 in flight
        #pragma unroll
        for (int i = 0; i < 4; i += 2) {
            __half2 h[4];
            h[0] = __floats2half2_rn(v[i].x, v[i].y);
            h[1] = __floats2half2_rn(v[i].z, v[i].w);
            h[2] = __floats2half2_rn(v[i + 1].x, v[i + 1].y);
            h[3] = __floats2half2_rn(v[i + 1].z, v[i + 1].w);
            reinterpret_cast<uint4*>(A16)[(size_t)t * 2 + (i >> 1)] =
                *reinterpret_cast<uint4*>(h);
        }
    } else {
        int t = (bid - NBLK_A) * 256 + threadIdx.x;
        int k16 = t & (Kdim / 16 - 1);
        int n = t >> 8;
        int g = k16 >> 3;
        float s = sc[n * Gdim + g];
        float z = zr[n * Gdim + g];
        const int4* qp = reinterpret_cast<const int4*>(q) + (size_t)t * 4;
        int4 v[4];
        #pragma unroll
        for (int i = 0; i < 4; i++) v[i] = qp[i];
        #pragma unroll
        for (int i = 0; i < 4; i += 2) {
            __half2 h[4];
            h[0] = __floats2half2_rn(((float)v[i].x - z) * s, ((float)v[i].y - z) * s);
            h[1] = __floats2half2_rn(((float)v[i].z - z) * s, ((float)v[i].w - z) * s);
            h[2] = __floats2half2_rn(((float)v[i+1].x - z) * s, ((float)v[i+1].y - z) * s);
            h[3] = __floats2half2_rn(((float)v[i+1].z - z) * s, ((float)v[i+1].w - z) * s);
            reinterpret_cast<uint4*>(W16)[(size_t)t * 2 + (i >> 1)] =
                *reinterpret_cast<uint4*>(h);
        }
    }
}

// ---------------------------- Pass 2: GEMM ----------------------------------
// 128 threads = 4 warps (2x2), warp tile 64x32, CTA tile 128x64, 4 CTAs/SM.
// Each SMSP hosts one warp from each of the 4 resident CTAs -> 4 independent
// instruction streams per scheduler.
__global__ void __launch_bounds__(128, 4)
gemm_f16_kernel(const __grid_constant__ CUtensorMap tmA,
                const __grid_constant__ CUtensorMap tmB,
                const float* __restrict__ bias,
                float* __restrict__ out) {
    extern __shared__ char smem[];
    uint32_t sb = smem_u32(smem);
    int tid = threadIdx.x, wid = tid >> 5, lane = tid & 31;
    int bn = blockIdx.x, bm = blockIdx.y;
    int wm = wid >> 1, wn = wid & 1;  // warp coords: 2(M) x 2(N)

    if (tid == 0) {
        #pragma unroll
        for (int i = 0; i < STAGES; i++) mbar_init(sb + OFF_FULL + i * 8, 1);
        fence_proxy_async();
    }
    __syncthreads();

    // Prologue: fill both stages
    if (tid == 0) {
        #pragma unroll
        for (int j = 0; j < STAGES; j++) {
            uint32_t fullb = sb + OFF_FULL + j * 8;
            uint32_t sA = sb + OFF_STAGE + j * STAGE_BYTES;
            mbar_expect_tx(fullb, STAGE_BYTES);
            tma_2d(sA, &tmA, j * TILE_K, bm * TILE_M, fullb);
            tma_2d(sA + A_STAGE_BYTES, &tmB, j * TILE_K, bn * TILE_N, fullb);
        }
    }

    // ldmatrix address components (SW128: xor = (lane&7)*16)
    int a_row = wm * 64 + (lane & 15);                      // + mb*16, <=127
    int a_khalf = (lane & 16);
    int b_row = wn * 32 + ((lane & 16) >> 1) + (lane & 7);  // + j*16, <=63
    int b_khalf = (lane & 8) << 1;
    int sw_xor = (lane & 7) * 16;

    uint32_t aRowOff[4], bRowOff[2];
    #pragma unroll
    for (int mb = 0; mb < 4; mb++) aRowOff[mb] = (uint32_t)(a_row + mb * 16) * 128;
    #pragma unroll
    for (int j = 0; j < 2; j++)
        bRowOff[j] = A_STAGE_BYTES + (uint32_t)(b_row + j * 16) * 128;

    float acc[4][4][4];
    #pragma unroll
    for (int mb = 0; mb < 4; mb++)
        #pragma unroll
        for (int nb = 0; nb < 4; nb++)
            #pragma unroll
            for (int i = 0; i < 4; i++) acc[mb][nb][i] = 0.0f;

    for (int s = 0; s < NUM_SLABS; s++) {
        int st = s & 1;
        int ph = (s >> 1) & 1;
        mbar_wait(sb + OFF_FULL + st * 8, ph);
        uint32_t base = sb + OFF_STAGE + st * STAGE_BYTES;

        #pragma unroll
        for (int ks = 0; ks < 4; ks++) {
            int koffA = ((ks * 32) | a_khalf) ^ sw_xor;
            int koffB = ((ks * 32) | b_khalf) ^ sw_xor;
            uint32_t a[4][4], b[2][4];
            #pragma unroll
            for (int mb = 0; mb < 4; mb++)
                ldsm_x4(a[mb][0], a[mb][1], a[mb][2], a[mb][3],
                        base + aRowOff[mb] + koffA);
            #pragma unroll
            for (int j = 0; j < 2; j++)
                ldsm_x4(b[j][0], b[j][1], b[j][2], b[j][3],
                        base + bRowOff[j] + koffB);
            #pragma unroll
            for (int mb = 0; mb < 4; mb++) {
                #pragma unroll
                for (int nb = 0; nb < 4; nb++) {
                    int j = nb >> 1, h = (nb & 1) * 2;
                    mma16816(acc[mb][nb], a[mb], b[j][h], b[j][h + 1]);
                }
            }
        }

        // stage fully consumed -> one barrier, tid0 refills for slab s+2
        __syncthreads();
        if (tid == 0 && s + STAGES < NUM_SLABS) {
            uint32_t fullb = sb + OFF_FULL + st * 8;
            mbar_expect_tx(fullb, STAGE_BYTES);
            tma_2d(base, &tmA, (s + STAGES) * TILE_K, bm * TILE_M, fullb);
            tma_2d(base + A_STAGE_BYTES, &tmB, (s + STAGES) * TILE_K,
                   bn * TILE_N, fullb);
        }
    }

    // ---------------- epilogue ----------------
    int gr = lane >> 2, gc = (lane & 3) * 2;
    #pragma unroll
    for (int mb = 0; mb < 4; mb++) {
        int row = bm * TILE_M + wm * 64 + mb * 16 + gr;
        float* orow0 = out + (size_t)row * Ndim;
        float* orow1 = out + (size_t)(row + 8) * Ndim;
        #pragma unroll
        for (int nb = 0; nb < 4; nb++) {
            int col = bn * TILE_N + wn * 32 + nb * 8 + gc;
            float2 bv = __ldg(reinterpret_cast<const float2*>(bias + col));
            float2 v0 = {acc[mb][nb][0] + bv.x, acc[mb][nb][1] + bv.y};
            float2 v1 = {acc[mb][nb][2] + bv.x, acc[mb][nb][3] + bv.y};
            *reinterpret_cast<float2*>(orow0 + col) = v0;
            *reinterpret_cast<float2*>(orow1 + col) = v1;
        }
    }
}

// ---------------------------- host launch -----------------------------------
typedef CUresult (*PFN_encodeTiled)(
    CUtensorMap*, CUtensorMapDataType, cuuint32_t, void*,
    const cuuint64_t*, const cuuint64_t*, const cuuint32_t*, const cuuint32_t*,
    CUtensorMapInterleave, CUtensorMapSwizzle, CUtensorMapL2promotion,
    CUtensorMapFloatOOBfill);

extern "C" void kernel_launch(void* const* d_in, const int* in_sizes, int n_in,
                              void* d_out, int out_size) {
    const float* A      = (const float*)d_in[0];
    const int*   qw     = (const int*)  d_in[1];
    const float* scales = (const float*)d_in[2];
    const float* zeros  = (const float*)d_in[3];
    const float* bias   = (const float*)d_in[4];
    float*       out    = (float*)d_out;

    void *pA16 = nullptr, *pW16 = nullptr;
    cudaGetSymbolAddress(&pA16, g_A16);
    cudaGetSymbolAddress(&pW16, g_W16);
    __half* A16 = (__half*)pA16;
    __half* W16 = (__half*)pW16;

    pass1_kernel<<<NBLK_A + NBLK_W, 256>>>(A, qw, scales, zeros, A16, W16);

    PFN_encodeTiled enc = nullptr;
    cudaDriverEntryPointQueryResult qres;
    cudaGetDriverEntryPointByVersion("cuTensorMapEncodeTiled", (void**)&enc,
                                     12000, cudaEnableDefault, &qres);
    if (!enc) return;

    CUtensorMap tmA, tmB;
    {
        cuuint64_t dims[2]    = {(cuuint64_t)Kdim, (cuuint64_t)Mdim};
        cuuint64_t strides[1] = {(cuuint64_t)Kdim * 2};
        cuuint32_t box[2]     = {TILE_K, TILE_M};  // {64, 128}
        cuuint32_t es[2]      = {1, 1};
        enc(&tmA, CU_TENSOR_MAP_DATA_TYPE_FLOAT16, 2, A16, dims, strides, box, es,
            CU_TENSOR_MAP_INTERLEAVE_NONE, CU_TENSOR_MAP_SWIZZLE_128B,
            CU_TENSOR_MAP_L2_PROMOTION_L2_128B, CU_TENSOR_MAP_FLOAT_OOB_FILL_NONE);
    }
    {
        cuuint64_t dims[2]    = {(cuuint64_t)Kdim, (cuuint64_t)Ndim};
        cuuint64_t strides[1] = {(cuuint64_t)Kdim * 2};
        cuuint32_t box[2]     = {TILE_K, TILE_N};  // {64, 64}
        cuuint32_t es[2]      = {1, 1};
        enc(&tmB, CU_TENSOR_MAP_DATA_TYPE_FLOAT16, 2, W16, dims, strides, box, es,
            CU_TENSOR_MAP_INTERLEAVE_NONE, CU_TENSOR_MAP_SWIZZLE_128B,
            CU_TENSOR_MAP_L2_PROMOTION_L2_128B, CU_TENSOR_MAP_FLOAT_OOB_FILL_NONE);
    }

    cudaFuncSetAttribute(gemm_f16_kernel,
                         cudaFuncAttributeMaxDynamicSharedMemorySize, SMEM_TOTAL);
    dim3 grid(Ndim / TILE_N, Mdim / TILE_M);  // (64, 16) = 1024 tiles
    gemm_f16_kernel<<<grid, 128, SMEM_TOTAL>>>(tmA, tmB, bias, out);
}